// round 4
// baseline (speedup 1.0000x reference)
#include <cuda_runtime.h>
#include <cstdint>

// Problem constants
#define Bc 2
#define Hc 16
#define Sc 2048
#define Dc 64
#define ROWS 32          // q-rows per block (== warp lanes)
#define TILE 64          // keys per smem tile
#define NT (Sc / TILE)   // 32 tiles
#define KPW 8            // keys per warp per tile (8 warps * 8 = 64)
#define SCALEF 0.125f    // 1/sqrt(64)
#define LOG2E 1.4426950408889634f

__global__ __launch_bounds__(256)
void attn_fused_kernel(const float* __restrict__ Q,
                       const float* __restrict__ K,
                       const float* __restrict__ V,
                       const int*   __restrict__ M,   // attention_mask materialized as int32
                       float* __restrict__ Octx,
                       float* __restrict__ Oattn)
{
    __shared__ float   Kt[TILE][Dc + 4];     // K tile (P1) / V tile (P2)
    __shared__ float   St[ROWS][TILE + 1];   // score staging tile
    __shared__ float   Ct[ROWS][Dc + 1];     // context accumulator
    __shared__ uint8_t Mt[ROWS][TILE + 4];   // mask tile; stride 68B = 17 words, gcd(17,32)=1 -> conflict-free
    __shared__ float   wred[8][ROWS];        // per-warp partial max / sum
    __shared__ float   mrow[ROWS];
    __shared__ float   invl[ROWS];

    const int tid  = threadIdx.x;
    const int w    = tid >> 5;
    const int lane = tid & 31;
    const int q0   = blockIdx.x * ROWS;
    const int hh   = blockIdx.y;
    const int bb   = blockIdx.z;

    const long long bh = (long long)(bb * Hc + hh);
    const float* Qbase = Q + (bh * Sc + q0) * Dc;
    const float* Kbase = K + bh * Sc * Dc;
    const float* Vbase = V + bh * Sc * Dc;
    const int*   Mbase = M + ((long long)bb * Sc + q0) * Sc;   // mask is [B,1,S,S] int32
    float* Arow = Oattn + (bh * Sc + q0) * (long long)Sc;      // this block's ROWS x S slab
    float* Crow = Octx  + (bh * Sc + q0) * (long long)Dc;

    // Each lane owns one q-row; keep it in registers.
    float qreg[Dc];
    {
        const float4* qp = reinterpret_cast<const float4*>(Qbase + lane * Dc);
        #pragma unroll
        for (int c = 0; c < Dc / 4; c++) {
            float4 v = qp[c];
            qreg[4*c+0] = v.x; qreg[4*c+1] = v.y; qreg[4*c+2] = v.z; qreg[4*c+3] = v.w;
        }
    }

    // ---------------- Phase 1: masked raw scores -> gmem, track row max ----------------
    float mmax = -3.0e38f;
    for (int t = 0; t < NT; t++) {
        __syncthreads();   // protect Kt/St/Mt from previous iteration's readers
        // Cooperative K tile load: 1024 float4, coalesced
        {
            const float4* kg = reinterpret_cast<const float4*>(Kbase + t * TILE * Dc);
            #pragma unroll
            for (int i = 0; i < 4; i++) {
                int f = tid + i * 256;
                int key = f >> 4, c = f & 15;
                float4 v = kg[f];
                *reinterpret_cast<float4*>(&Kt[key][c * 4]) = v;
            }
            // Mask tile: 2048 int32 -> bytes in smem. Coalesced 1KB per iteration.
            #pragma unroll
            for (int i = 0; i < 8; i++) {
                int u = tid + i * 256;
                int r = u >> 6, c = u & 63;
                Mt[r][c] = (uint8_t)(Mbase[(long long)r * Sc + t * TILE + c] != 0);
            }
        }
        __syncthreads();

        #pragma unroll
        for (int kk = 0; kk < KPW; kk++) {
            int j = w * KPW + kk;
            const float4* kr = reinterpret_cast<const float4*>(&Kt[j][0]);  // broadcast reads
            float a0 = 0.f, a1 = 0.f, a2 = 0.f, a3 = 0.f;
            #pragma unroll
            for (int c = 0; c < 16; c++) {
                float4 v = kr[c];
                a0 = fmaf(qreg[4*c+0], v.x, a0);
                a1 = fmaf(qreg[4*c+1], v.y, a1);
                a2 = fmaf(qreg[4*c+2], v.z, a2);
                a3 = fmaf(qreg[4*c+3], v.w, a3);
            }
            float s = ((a0 + a1) + (a2 + a3)) * SCALEF;
            if (Mt[lane][j]) s = -1e9f;   // mask TRUE -> -1e9
            mmax = fmaxf(mmax, s);
            St[lane][j] = s;
        }
        __syncthreads();
        // Coalesced raw-score store
        #pragma unroll
        for (int i = 0; i < 8; i++) {
            int e = tid + i * 256;
            int r = e >> 6, c = e & 63;
            Arow[(long long)r * Sc + t * TILE + c] = St[r][c];
        }
    }
    wred[w][lane] = mmax;
    __syncthreads();
    if (tid < ROWS) {
        float m = wred[0][tid];
        #pragma unroll
        for (int x = 1; x < 8; x++) m = fmaxf(m, wred[x][tid]);
        mrow[tid] = m;
    }
    for (int e = tid; e < ROWS * (Dc + 1); e += 256) (&Ct[0][0])[e] = 0.f;
    __syncthreads();

    // ---------------- Phase 2: exp + l-sum + P@V ----------------
    float ctx[Dc];
    #pragma unroll
    for (int c = 0; c < Dc; c++) ctx[c] = 0.f;
    float lsum = 0.f;
    const float mlane = mrow[lane];

    for (int t = 0; t < NT; t++) {
        __syncthreads();
        {   // V tile into Kt buffer
            const float4* vg = reinterpret_cast<const float4*>(Vbase + t * TILE * Dc);
            #pragma unroll
            for (int i = 0; i < 4; i++) {
                int f = tid + i * 256;
                int key = f >> 4, c = f & 15;
                float4 v = vg[f];
                *reinterpret_cast<float4*>(&Kt[key][c * 4]) = v;
            }
            // raw score tile back from gmem (L2-hot), coalesced
            #pragma unroll
            for (int i = 0; i < 8; i++) {
                int e = tid + i * 256;
                int r = e >> 6, c = e & 63;
                St[r][c] = Arow[(long long)r * Sc + t * TILE + c];
            }
        }
        __syncthreads();

        #pragma unroll
        for (int kk = 0; kk < KPW; kk++) {
            int j = w * KPW + kk;
            float p = exp2f((St[lane][j] - mlane) * LOG2E);
            lsum += p;
            const float4* vr = reinterpret_cast<const float4*>(&Kt[j][0]);
            #pragma unroll
            for (int c = 0; c < 16; c++) {
                float4 v = vr[c];
                ctx[4*c+0] = fmaf(p, v.x, ctx[4*c+0]);
                ctx[4*c+1] = fmaf(p, v.y, ctx[4*c+1]);
                ctx[4*c+2] = fmaf(p, v.z, ctx[4*c+2]);
                ctx[4*c+3] = fmaf(p, v.w, ctx[4*c+3]);
            }
        }
    }
    wred[w][lane] = lsum;
    #pragma unroll
    for (int c = 0; c < Dc; c++) atomicAdd(&Ct[lane][c], ctx[c]);   // distinct rows per lane
    __syncthreads();
    if (tid < ROWS) {
        float l = wred[0][tid];
        #pragma unroll
        for (int x = 1; x < 8; x++) l += wred[x][tid];
        invl[tid] = 1.f / l;
    }
    __syncthreads();

    // Write normalized context (coalesced)
    #pragma unroll
    for (int i = 0; i < 8; i++) {
        int e = tid + i * 256;
        int r = e >> 6, c = e & 63;
        Crow[(long long)r * Dc + c] = Ct[r][c] * invl[r];
    }

    // ---------------- Phase 3: normalize attention in place ----------------
    // ROWS*Sc = 65536 floats = 16384 float4, 64 per thread
    #pragma unroll 4
    for (int i = 0; i < 64; i++) {
        int g  = tid + i * 256;
        int r  = g >> 9;          // 512 float4 per row
        int c4 = g & 511;
        float4* ap = reinterpret_cast<float4*>(Arow + (long long)r * Sc) + c4;
        float4 s = *ap;
        float m = mrow[r], il = invl[r];
        s.x = exp2f((s.x - m) * LOG2E) * il;
        s.y = exp2f((s.y - m) * LOG2E) * il;
        s.z = exp2f((s.z - m) * LOG2E) * il;
        s.w = exp2f((s.w - m) * LOG2E) * il;
        *ap = s;
    }
}

extern "C" void kernel_launch(void* const* d_in, const int* in_sizes, int n_in,
                              void* d_out, int out_size)
{
    const float* Q = (const float*)d_in[0];
    const float* K = (const float*)d_in[1];
    const float* V = (const float*)d_in[2];
    const int*   M = (const int*)d_in[3];   // boolean mask materialized as int32
    (void)in_sizes; (void)n_in; (void)out_size;

    // Output tuple (context, attention): context first, attention after.
    float* ctx  = (float*)d_out;
    float* attn = (float*)d_out + (size_t)Bc * Hc * Sc * Dc;

    dim3 grid(Sc / ROWS, Hc, Bc);   // (64, 16, 2)
    attn_fused_kernel<<<grid, 256>>>(Q, K, V, M, ctx, attn);
}

// round 5
// speedup vs baseline: 1.4647x; 1.4647x over previous
#include <cuda_runtime.h>
#include <cstdint>

// Problem constants
#define Bc 2
#define Hc 16
#define Sc 2048
#define Dc 64
#define ROWS 32          // q-rows per block (== warp lanes)
#define TILE 64          // keys per smem tile
#define NT (Sc / TILE)   // 32 tiles
#define KPW 8            // keys per warp per tile (8 warps * 8 = 64)
#define SCALEF 0.125f    // 1/sqrt(64)
#define LOG2E 1.4426950408889634f

// ---- packed f32x2 helpers (FFMA2 path; ptxas won't auto-fuse) ----
__device__ __forceinline__ void fma2(uint64_t& d, uint64_t a, uint64_t b) {
    asm("fma.rn.f32x2 %0, %1, %2, %0;" : "+l"(d) : "l"(a), "l"(b));
}
__device__ __forceinline__ uint64_t pack2(float lo, float hi) {
    uint64_t r; asm("mov.b64 %0, {%1, %2};" : "=l"(r) : "f"(lo), "f"(hi)); return r;
}
__device__ __forceinline__ void unpack2(uint64_t v, float& lo, float& hi) {
    asm("mov.b64 {%0, %1}, %2;" : "=f"(lo), "=f"(hi) : "l"(v));
}
__device__ __forceinline__ float ex2(float x) {
    float r; asm("ex2.approx.ftz.f32 %0, %1;" : "=f"(r) : "f"(x)); return r;
}

__global__ __launch_bounds__(256, 2)
void attn_fused_kernel(const float* __restrict__ Q,
                       const float* __restrict__ K,
                       const float* __restrict__ V,
                       const int*   __restrict__ M,   // attention_mask materialized as int32
                       float* __restrict__ Octx,
                       float* __restrict__ Oattn)
{
    __shared__ __align__(16) float Kt[TILE][Dc + 4];   // K tile (P1) / V tile (P2); row = 272B (16B-aligned)
    __shared__ float   St[ROWS][TILE + 1];             // score / prob staging tile
    __shared__ float   Ct[ROWS][Dc + 1];               // context accumulator
    __shared__ uint8_t Mt[ROWS][TILE + 4];             // mask tile (stride 68B, conflict-free)
    __shared__ float   wm[8][ROWS];                    // per-warp running max
    __shared__ float   wl[8][ROWS];                    // per-warp running sumexp
    __shared__ float   mrow[ROWS];
    __shared__ float   invl[ROWS];

    const int tid  = threadIdx.x;
    const int w    = tid >> 5;
    const int lane = tid & 31;
    const int q0   = blockIdx.x * ROWS;
    const int hh   = blockIdx.y;
    const int bb   = blockIdx.z;

    const long long bh = (long long)(bb * Hc + hh);
    const float* Qbase = Q + (bh * Sc + q0) * Dc;
    const float* Kbase = K + bh * Sc * Dc;
    const float* Vbase = V + bh * Sc * Dc;
    const int*   Mbase = M + ((long long)bb * Sc + q0) * Sc;   // mask is [B,1,S,S] int32
    float* Arow = Oattn + (bh * Sc + q0) * (long long)Sc;
    float* Crow = Octx  + (bh * Sc + q0) * (long long)Dc;

    // Each lane owns one q-row; keep it in packed f32x2 registers.
    uint64_t qpk[Dc / 2];
    {
        const ulonglong2* qp = reinterpret_cast<const ulonglong2*>(Qbase + lane * Dc);
        #pragma unroll
        for (int c = 0; c < Dc / 4; c++) {
            ulonglong2 v = qp[c];
            qpk[2*c]   = v.x;
            qpk[2*c+1] = v.y;
        }
    }

    // ---------------- Phase 1: masked raw scores -> gmem, online (m, l) ----------------
    float m = -3.0e38f;
    float l = 0.0f;
    for (int t = 0; t < NT; t++) {
        __syncthreads();   // protect Kt/St/Mt from previous iteration's readers
        {   // Cooperative K tile load: 1024 float4, coalesced
            const float4* kg = reinterpret_cast<const float4*>(Kbase + t * TILE * Dc);
            #pragma unroll
            for (int i = 0; i < 4; i++) {
                int f = tid + i * 256;
                int key = f >> 4, c = f & 15;
                float4 v = kg[f];
                *reinterpret_cast<float4*>(&Kt[key][c * 4]) = v;
            }
            // Mask tile: 2048 int32 -> bytes
            #pragma unroll
            for (int i = 0; i < 8; i++) {
                int u = tid + i * 256;
                int r = u >> 6, c = u & 63;
                Mt[r][c] = (uint8_t)(Mbase[(long long)r * Sc + t * TILE + c] != 0);
            }
        }
        __syncthreads();

        #pragma unroll
        for (int kk = 0; kk < KPW; kk++) {
            int j = w * KPW + kk;
            const ulonglong2* kr = reinterpret_cast<const ulonglong2*>(&Kt[j][0]);  // broadcast reads
            uint64_t a01 = 0ull, a23 = 0ull;
            #pragma unroll
            for (int c = 0; c < 16; c++) {
                ulonglong2 v = kr[c];
                fma2(a01, qpk[2*c],   v.x);
                fma2(a23, qpk[2*c+1], v.y);
            }
            float f0, f1, f2, f3;
            unpack2(a01, f0, f1);
            unpack2(a23, f2, f3);
            float s = ((f0 + f1) + (f2 + f3)) * SCALEF;
            if (Mt[lane][j]) s = -1e9f;   // mask TRUE -> -1e9
            St[lane][j] = s;
            // online softmax update (base-2)
            float mn = fmaxf(m, s);
            l = l * ex2((m - mn) * LOG2E) + ex2((s - mn) * LOG2E);
            m = mn;
        }
        __syncthreads();
        // Coalesced raw-score store
        #pragma unroll
        for (int i = 0; i < 8; i++) {
            int e = tid + i * 256;
            int r = e >> 6, c = e & 63;
            Arow[(long long)r * Sc + t * TILE + c] = St[r][c];
        }
    }
    wm[w][lane] = m;
    wl[w][lane] = l;
    __syncthreads();
    if (tid < ROWS) {
        float mf = wm[0][tid];
        #pragma unroll
        for (int x = 1; x < 8; x++) mf = fmaxf(mf, wm[x][tid]);
        float ls = 0.f;
        #pragma unroll
        for (int x = 0; x < 8; x++) ls += wl[x][tid] * ex2((wm[x][tid] - mf) * LOG2E);
        mrow[tid] = mf;
        invl[tid] = 1.f / ls;
    }
    for (int e = tid; e < ROWS * (Dc + 1); e += 256) (&Ct[0][0])[e] = 0.f;
    __syncthreads();

    // ---------------- Phase 2: normalized probs -> gmem (final), P@V ----------------
    uint64_t cpk[Dc / 2];
    #pragma unroll
    for (int c = 0; c < Dc / 2; c++) cpk[c] = 0ull;
    const float mlane = mrow[lane];
    const float il    = invl[lane];

    for (int t = 0; t < NT; t++) {
        __syncthreads();
        {   // V tile into Kt buffer
            const float4* vg = reinterpret_cast<const float4*>(Vbase + t * TILE * Dc);
            #pragma unroll
            for (int i = 0; i < 4; i++) {
                int f = tid + i * 256;
                int key = f >> 4, c = f & 15;
                float4 v = vg[f];
                *reinterpret_cast<float4*>(&Kt[key][c * 4]) = v;
            }
            // raw score tile back from gmem (L2-hot), coalesced
            #pragma unroll
            for (int i = 0; i < 8; i++) {
                int e = tid + i * 256;
                int r = e >> 6, c = e & 63;
                St[r][c] = Arow[(long long)r * Sc + t * TILE + c];
            }
        }
        __syncthreads();

        #pragma unroll
        for (int kk = 0; kk < KPW; kk++) {
            int j = w * KPW + kk;
            float p = ex2((St[lane][j] - mlane) * LOG2E) * il;   // fully normalized prob
            St[lane][j] = p;                                     // own element: no race
            uint64_t pp = pack2(p, p);
            const ulonglong2* vr = reinterpret_cast<const ulonglong2*>(&Kt[j][0]);
            #pragma unroll
            for (int c = 0; c < 16; c++) {
                ulonglong2 v = vr[c];
                fma2(cpk[2*c],   pp, v.x);
                fma2(cpk[2*c+1], pp, v.y);
            }
        }
        __syncthreads();
        // Final normalized attention store (coalesced) — written exactly once
        #pragma unroll
        for (int i = 0; i < 8; i++) {
            int e = tid + i * 256;
            int r = e >> 6, c = e & 63;
            Arow[(long long)r * Sc + t * TILE + c] = St[r][c];
        }
    }

    // Combine per-warp context partials (already normalized by il)
    #pragma unroll
    for (int c = 0; c < Dc / 2; c++) {
        float f0, f1;
        unpack2(cpk[c], f0, f1);
        atomicAdd(&Ct[lane][2*c],     f0);
        atomicAdd(&Ct[lane][2*c + 1], f1);
    }
    __syncthreads();

    // Write context (coalesced)
    #pragma unroll
    for (int i = 0; i < 8; i++) {
        int e = tid + i * 256;
        int r = e >> 6, c = e & 63;
        Crow[(long long)r * Dc + c] = Ct[r][c];
    }
}

extern "C" void kernel_launch(void* const* d_in, const int* in_sizes, int n_in,
                              void* d_out, int out_size)
{
    const float* Q = (const float*)d_in[0];
    const float* K = (const float*)d_in[1];
    const float* V = (const float*)d_in[2];
    const int*   M = (const int*)d_in[3];   // boolean mask materialized as int32
    (void)in_sizes; (void)n_in; (void)out_size;

    // Output tuple (context, attention): context first, attention after.
    float* ctx  = (float*)d_out;
    float* attn = (float*)d_out + (size_t)Bc * Hc * Sc * Dc;

    dim3 grid(Sc / ROWS, Hc, Bc);   // (64, 16, 2)
    attn_fused_kernel<<<grid, 256>>>(Q, K, V, M, ctx, attn);
}

// round 8
// speedup vs baseline: 1.4727x; 1.0054x over previous
#include <cuda_runtime.h>
#include <cstdint>

// Problem constants
#define Bc 2
#define Hc 16
#define Sc 2048
#define Dc 64
#define ROWS 32          // q-rows per block (== warp lanes)
#define TILE 64          // keys per smem tile
#define NT (Sc / TILE)   // 32 tiles
#define KPW 8            // keys per warp per tile (8 warps * 8 = 64)
#define SCALEF 0.125f    // 1/sqrt(64)
#define LOG2E 1.4426950408889634f

// ---- packed f32x2 helpers (FFMA2 path; ptxas won't auto-fuse) ----
__device__ __forceinline__ void fma2(uint64_t& d, uint64_t a, uint64_t b) {
    asm("fma.rn.f32x2 %0, %1, %2, %0;" : "+l"(d) : "l"(a), "l"(b));
}
__device__ __forceinline__ uint64_t pack2(float lo, float hi) {
    uint64_t r; asm("mov.b64 %0, {%1, %2};" : "=l"(r) : "f"(lo), "f"(hi)); return r;
}
__device__ __forceinline__ void unpack2(uint64_t v, float& lo, float& hi) {
    asm("mov.b64 {%0, %1}, %2;" : "=f"(lo), "=f"(hi) : "l"(v));
}
__device__ __forceinline__ float ex2(float x) {
    float r; asm("ex2.approx.ftz.f32 %0, %1;" : "=f"(r) : "f"(x)); return r;
}

__global__ __launch_bounds__(256, 2)
void attn_fused_kernel(const float* __restrict__ Q,
                       const float* __restrict__ K,
                       const float* __restrict__ V,
                       const int*   __restrict__ M,   // attention_mask materialized as int32
                       float* __restrict__ Octx,
                       float* __restrict__ Oattn)
{
    __shared__ __align__(16) float Kt[TILE][Dc + 4];   // K tile (P1) / V tile (P2); row = 272B (16B-aligned)
    __shared__ float   St[ROWS][TILE + 1];             // score / prob staging tile
    __shared__ float   Ct[ROWS][Dc + 1];               // context accumulator
    __shared__ uint8_t Mt[ROWS][TILE + 4];             // mask tile (stride 68B, conflict-free)
    __shared__ float   wm[8][ROWS];                    // per-warp running max
    __shared__ float   wl[8][ROWS];                    // per-warp running sumexp
    __shared__ float   mrow[ROWS];
    __shared__ float   invl[ROWS];

    const int tid  = threadIdx.x;
    const int w    = tid >> 5;
    const int lane = tid & 31;
    const int q0   = blockIdx.x * ROWS;
    const int hh   = blockIdx.y;
    const int bb   = blockIdx.z;

    const long long bh = (long long)(bb * Hc + hh);
    const float* Qbase = Q + (bh * Sc + q0) * Dc;
    const float* Kbase = K + bh * Sc * Dc;
    const float* Vbase = V + bh * Sc * Dc;
    const int*   Mbase = M + ((long long)bb * Sc + q0) * Sc;   // mask is [B,1,S,S] int32
    float* Arow = Oattn + (bh * Sc + q0) * (long long)Sc;
    float* Crow = Octx  + (bh * Sc + q0) * (long long)Dc;

    // Each lane owns one q-row; keep it in packed f32x2 registers.
    uint64_t qpk[Dc / 2];
    {
        const ulonglong2* qp = reinterpret_cast<const ulonglong2*>(Qbase + lane * Dc);
        #pragma unroll
        for (int c = 0; c < Dc / 4; c++) {
            ulonglong2 v = qp[c];
            qpk[2*c]   = v.x;
            qpk[2*c+1] = v.y;
        }
    }

    // ---------------- Phase 1: masked raw scores -> gmem, online (m, l) ----------------
    float m = -3.0e38f;
    float l = 0.0f;
    for (int t = 0; t < NT; t++) {
        __syncthreads();   // protect Kt/St/Mt from previous iteration's readers
        {   // Cooperative K tile load: 1024 float4, coalesced
            const float4* kg = reinterpret_cast<const float4*>(Kbase + t * TILE * Dc);
            #pragma unroll
            for (int i = 0; i < 4; i++) {
                int f = tid + i * 256;
                int key = f >> 4, c = f & 15;
                float4 v = kg[f];
                *reinterpret_cast<float4*>(&Kt[key][c * 4]) = v;
            }
            // Mask tile: 2048 int32 -> bytes
            #pragma unroll
            for (int i = 0; i < 8; i++) {
                int u = tid + i * 256;
                int r = u >> 6, c = u & 63;
                Mt[r][c] = (uint8_t)(Mbase[(long long)r * Sc + t * TILE + c] != 0);
            }
        }
        __syncthreads();

        #pragma unroll
        for (int kk = 0; kk < KPW; kk++) {
            int j = w * KPW + kk;
            const ulonglong2* kr = reinterpret_cast<const ulonglong2*>(&Kt[j][0]);  // broadcast reads
            uint64_t a01 = 0ull, a23 = 0ull;
            #pragma unroll
            for (int c = 0; c < 16; c++) {
                ulonglong2 v = kr[c];
                fma2(a01, qpk[2*c],   v.x);
                fma2(a23, qpk[2*c+1], v.y);
            }
            float f0, f1, f2, f3;
            unpack2(a01, f0, f1);
            unpack2(a23, f2, f3);
            float s = ((f0 + f1) + (f2 + f3)) * SCALEF;
            if (Mt[lane][j]) s = -1e9f;   // mask TRUE -> -1e9
            St[lane][j] = s;
            // online softmax update (base-2)
            float mn = fmaxf(m, s);
            l = l * ex2((m - mn) * LOG2E) + ex2((s - mn) * LOG2E);
            m = mn;
        }
        __syncthreads();
        // Coalesced raw-score store
        #pragma unroll
        for (int i = 0; i < 8; i++) {
            int e = tid + i * 256;
            int r = e >> 6, c = e & 63;
            Arow[(long long)r * Sc + t * TILE + c] = St[r][c];
        }
    }
    wm[w][lane] = m;
    wl[w][lane] = l;
    __syncthreads();
    if (tid < ROWS) {
        float mf = wm[0][tid];
        #pragma unroll
        for (int x = 1; x < 8; x++) mf = fmaxf(mf, wm[x][tid]);
        float ls = 0.f;
        #pragma unroll
        for (int x = 0; x < 8; x++) ls += wl[x][tid] * ex2((wm[x][tid] - mf) * LOG2E);
        mrow[tid] = mf;
        invl[tid] = 1.f / ls;
    }
    for (int e = tid; e < ROWS * (Dc + 1); e += 256) (&Ct[0][0])[e] = 0.f;
    __syncthreads();

    // ---------------- Phase 2: normalized probs -> gmem (final), P@V ----------------
    uint64_t cpk[Dc / 2];
    #pragma unroll
    for (int c = 0; c < Dc / 2; c++) cpk[c] = 0ull;
    const float mlane = mrow[lane];
    const float il    = invl[lane];

    for (int t = 0; t < NT; t++) {
        __syncthreads();
        {   // V tile into Kt buffer
            const float4* vg = reinterpret_cast<const float4*>(Vbase + t * TILE * Dc);
            #pragma unroll
            for (int i = 0; i < 4; i++) {
                int f = tid + i * 256;
                int key = f >> 4, c = f & 15;
                float4 v = vg[f];
                *reinterpret_cast<float4*>(&Kt[key][c * 4]) = v;
            }
            // raw score tile back from gmem (L2-hot), coalesced
            #pragma unroll
            for (int i = 0; i < 8; i++) {
                int e = tid + i * 256;
                int r = e >> 6, c = e & 63;
                St[r][c] = Arow[(long long)r * Sc + t * TILE + c];
            }
        }
        __syncthreads();

        #pragma unroll
        for (int kk = 0; kk < KPW; kk++) {
            int j = w * KPW + kk;
            float p = ex2((St[lane][j] - mlane) * LOG2E) * il;   // fully normalized prob
            St[lane][j] = p;                                     // own element: no race
            uint64_t pp = pack2(p, p);
            const ulonglong2* vr = reinterpret_cast<const ulonglong2*>(&Kt[j][0]);
            #pragma unroll
            for (int c = 0; c < 16; c++) {
                ulonglong2 v = vr[c];
                fma2(cpk[2*c],   pp, v.x);
                fma2(cpk[2*c+1], pp, v.y);
            }
        }
        __syncthreads();
        // Final normalized attention store (coalesced) — written exactly once
        #pragma unroll
        for (int i = 0; i < 8; i++) {
            int e = tid + i * 256;
            int r = e >> 6, c = e & 63;
            Arow[(long long)r * Sc + t * TILE + c] = St[r][c];
        }
    }

    // Combine per-warp context partials (already normalized by il)
    #pragma unroll
    for (int c = 0; c < Dc / 2; c++) {
        float f0, f1;
        unpack2(cpk[c], f0, f1);
        atomicAdd(&Ct[lane][2*c],     f0);
        atomicAdd(&Ct[lane][2*c + 1], f1);
    }
    __syncthreads();

    // Write context (coalesced)
    #pragma unroll
    for (int i = 0; i < 8; i++) {
        int e = tid + i * 256;
        int r = e >> 6, c = e & 63;
        Crow[(long long)r * Dc + c] = Ct[r][c];
    }
}

extern "C" void kernel_launch(void* const* d_in, const int* in_sizes, int n_in,
                              void* d_out, int out_size)
{
    const float* Q = (const float*)d_in[0];
    const float* K = (const float*)d_in[1];
    const float* V = (const float*)d_in[2];
    const int*   M = (const int*)d_in[3];   // boolean mask materialized as int32
    (void)in_sizes; (void)n_in; (void)out_size;

    // Output tuple (context, attention): context first, attention after.
    float* ctx  = (float*)d_out;
    float* attn = (float*)d_out + (size_t)Bc * Hc * Sc * Dc;

    dim3 grid(Sc / ROWS, Hc, Bc);   // (64, 16, 2)
    attn_fused_kernel<<<grid, 256>>>(Q, K, V, M, ctx, attn);
}

// round 9
// speedup vs baseline: 2.1645x; 1.4698x over previous
#include <cuda_runtime.h>
#include <cstdint>

// Problem constants
#define Bc 2
#define Hc 16
#define Sc 2048
#define Dc 64
#define ROWS 64          // q-rows per block; each lane owns rows (lane, lane+32)
#define TILE 64          // keys per smem tile
#define NT (Sc / TILE)   // 32 tiles
#define KPW 8            // keys per warp per tile
#define SCALEF 0.125f    // 1/sqrt(64)
#define LOG2E 1.4426950408889634f

// smem layout (floats unless noted)
#define KT_OFF   0                       // Kt[64][64]      16384 B
#define ST_OFF   (KT_OFF + 64*64)        // St[64][68]      17408 B
#define QS_OFF   (ST_OFF + 64*68)        // Qs[64][68]      17408 B
#define MT_OFF   ((QS_OFF + 64*68)*4)    // Mt[64][68] u8    4352 B (byte offset)
#define WM_OFF   ((MT_OFF + 64*68)/4)    // wm[8][64]        2048 B (float idx)
#define WL_OFF   (WM_OFF + 8*64)
#define MR_OFF   (WL_OFF + 8*64)         // mrow[64]
#define IL_OFF   (MR_OFF + 64)           // invl[64]
#define SMEM_BYTES ((IL_OFF + 64) * 4)   // 60160 B

#define KT(r,c) sK[(r)*64 + (c)]
#define ST(r,c) sS[(r)*68 + (c)]
#define QS(r,c) sQ[(r)*68 + (c)]

// ---- packed f32x2 helpers ----
__device__ __forceinline__ void fma2(uint64_t& d, uint64_t a, uint64_t b) {
    asm("fma.rn.f32x2 %0, %1, %2, %0;" : "+l"(d) : "l"(a), "l"(b));
}
__device__ __forceinline__ uint64_t pack2(float lo, float hi) {
    uint64_t r; asm("mov.b64 %0, {%1, %2};" : "=l"(r) : "f"(lo), "f"(hi)); return r;
}
__device__ __forceinline__ void unpack2(uint64_t v, float& lo, float& hi) {
    asm("mov.b64 {%0, %1}, %2;" : "=f"(lo), "=f"(hi) : "l"(v));
}
__device__ __forceinline__ float ex2(float x) {
    float r; asm("ex2.approx.ftz.f32 %0, %1;" : "=f"(r) : "f"(x)); return r;
}

__global__ __launch_bounds__(256, 2)
void attn_fused_kernel(const float* __restrict__ Q,
                       const float* __restrict__ K,
                       const float* __restrict__ V,
                       const int*   __restrict__ M,
                       float* __restrict__ Octx,
                       float* __restrict__ Oattn)
{
    extern __shared__ __align__(16) float smem[];
    float*   sK = smem + KT_OFF;
    float*   sS = smem + ST_OFF;
    float*   sQ = smem + QS_OFF;
    uint8_t* sM = reinterpret_cast<uint8_t*>(smem) + MT_OFF;
    float*   wm = smem + WM_OFF;
    float*   wl = smem + WL_OFF;
    float*   mrow = smem + MR_OFF;
    float*   invl = smem + IL_OFF;

    const int tid  = threadIdx.x;
    const int w    = tid >> 5;
    const int lane = tid & 31;
    const int q0   = blockIdx.x * ROWS;
    const long long bh = (long long)(blockIdx.z * Hc + blockIdx.y);

    const float* Qbase = Q + (bh * Sc + q0) * Dc;
    const float* Kbase = K + bh * Sc * Dc;
    const float* Vbase = V + bh * Sc * Dc;
    const int*   Mbase = M + ((long long)blockIdx.z * Sc + q0) * Sc;  // mask [B,1,S,S]
    float* Arow = Oattn + (bh * Sc + q0) * (long long)Sc;
    float* Crow = Octx  + (bh * Sc + q0) * (long long)Dc;

    const int r0 = lane, r1 = lane + 32;

    // ---- stage Q tile (64x64) into smem, stride 68 ----
    {
        const float4* qg = reinterpret_cast<const float4*>(Qbase);
        #pragma unroll
        for (int i = 0; i < 4; i++) {
            int f = tid + i * 256;
            int r = f >> 4, c = f & 15;
            *reinterpret_cast<float4*>(&QS(r, c * 4)) = qg[f];
        }
    }

    // ================ Phase 1: raw scores -> gmem, online (m,l) per row ================
    float m0 = -3.0e38f, l0 = 0.f, m1 = -3.0e38f, l1 = 0.f;

    for (int t = 0; t < NT; t++) {
        __syncthreads();
        {   // K tile: 1024 float4 coalesced
            const float4* kg = reinterpret_cast<const float4*>(Kbase + t * TILE * Dc);
            #pragma unroll
            for (int i = 0; i < 4; i++) {
                int f = tid + i * 256;
                int r = f >> 4, c = f & 15;
                *reinterpret_cast<float4*>(&KT(r, c * 4)) = kg[f];
            }
            // mask tile: 4096 int32 -> bytes
            #pragma unroll
            for (int i = 0; i < 16; i++) {
                int u = tid + i * 256;
                int r = u >> 6, c = u & 63;
                sM[r * 68 + c] = (uint8_t)(Mbase[(long long)r * Sc + t * TILE + c] != 0);
            }
        }
        __syncthreads();

        // 2 rows x 8 keys micro-GEMM; 32 independent FFMA2 chains
        uint64_t aA[KPW][2], aB[KPW][2];
        #pragma unroll
        for (int j = 0; j < KPW; j++) { aA[j][0]=0; aA[j][1]=0; aB[j][0]=0; aB[j][1]=0; }

        #pragma unroll
        for (int c = 0; c < 16; c++) {
            ulonglong2 qa = *reinterpret_cast<const ulonglong2*>(&QS(r0, 4 * c));
            ulonglong2 qb = *reinterpret_cast<const ulonglong2*>(&QS(r1, 4 * c));
            #pragma unroll
            for (int j = 0; j < KPW; j++) {
                ulonglong2 kv = *reinterpret_cast<const ulonglong2*>(&KT(w * KPW + j, 4 * c));
                fma2(aA[j][0], qa.x, kv.x);
                fma2(aA[j][1], qa.y, kv.y);
                fma2(aB[j][0], qb.x, kv.x);
                fma2(aB[j][1], qb.y, kv.y);
            }
        }

        // epilogue per row: mask, St write, tile-local (m,l) then merge
        {
            float sv[KPW];
            #pragma unroll
            for (int j = 0; j < KPW; j++) {
                float f0,f1,f2,f3;
                unpack2(aA[j][0], f0, f1);
                unpack2(aA[j][1], f2, f3);
                float s = ((f0+f1)+(f2+f3)) * SCALEF;
                if (sM[r0 * 68 + w * KPW + j]) s = -1e9f;
                sv[j] = s;
                ST(r0, w * KPW + j) = s;
            }
            float mt = sv[0];
            #pragma unroll
            for (int j = 1; j < KPW; j++) mt = fmaxf(mt, sv[j]);
            float lt = 0.f;
            #pragma unroll
            for (int j = 0; j < KPW; j++) lt += ex2((sv[j] - mt) * LOG2E);
            float mn = fmaxf(m0, mt);
            l0 = l0 * ex2((m0 - mn) * LOG2E) + lt * ex2((mt - mn) * LOG2E);
            m0 = mn;
        }
        {
            float sv[KPW];
            #pragma unroll
            for (int j = 0; j < KPW; j++) {
                float f0,f1,f2,f3;
                unpack2(aB[j][0], f0, f1);
                unpack2(aB[j][1], f2, f3);
                float s = ((f0+f1)+(f2+f3)) * SCALEF;
                if (sM[r1 * 68 + w * KPW + j]) s = -1e9f;
                sv[j] = s;
                ST(r1, w * KPW + j) = s;
            }
            float mt = sv[0];
            #pragma unroll
            for (int j = 1; j < KPW; j++) mt = fmaxf(mt, sv[j]);
            float lt = 0.f;
            #pragma unroll
            for (int j = 0; j < KPW; j++) lt += ex2((sv[j] - mt) * LOG2E);
            float mn = fmaxf(m1, mt);
            l1 = l1 * ex2((m1 - mn) * LOG2E) + lt * ex2((mt - mn) * LOG2E);
            m1 = mn;
        }
        __syncthreads();
        // raw score tile -> gmem (coalesced)
        #pragma unroll
        for (int i = 0; i < 16; i++) {
            int e = tid + i * 256;
            int r = e >> 6, c = e & 63;
            Arow[(long long)r * Sc + t * TILE + c] = ST(r, c);
        }
    }

    wm[w * 64 + r0] = m0;  wl[w * 64 + r0] = l0;
    wm[w * 64 + r1] = m1;  wl[w * 64 + r1] = l1;
    __syncthreads();
    if (tid < 64) {
        float mf = wm[tid];
        #pragma unroll
        for (int x = 1; x < 8; x++) mf = fmaxf(mf, wm[x * 64 + tid]);
        float ls = 0.f;
        #pragma unroll
        for (int x = 0; x < 8; x++) ls += wl[x * 64 + tid] * ex2((wm[x * 64 + tid] - mf) * LOG2E);
        mrow[tid] = mf;
        invl[tid] = 1.f / ls;
    }
    __syncthreads();
    const float ml0 = mrow[r0], il0 = invl[r0];
    const float ml1 = mrow[r1], il1 = invl[r1];

    // ================ Phase 2: normalized probs -> gmem, P@V ================
    // lane owns rows (r0, r1) x d-columns [w*8, w*8+8)
    uint64_t cA[4], cB[4];
    #pragma unroll
    for (int c = 0; c < 4; c++) { cA[c] = 0; cB[c] = 0; }

    for (int t = 0; t < NT; t++) {
        __syncthreads();
        {   // V tile
            const float4* vg = reinterpret_cast<const float4*>(Vbase + t * TILE * Dc);
            #pragma unroll
            for (int i = 0; i < 4; i++) {
                int f = tid + i * 256;
                int r = f >> 4, c = f & 15;
                *reinterpret_cast<float4*>(&KT(r, c * 4)) = vg[f];
            }
            // raw scores back (L2-hot)
            #pragma unroll
            for (int i = 0; i < 16; i++) {
                int e = tid + i * 256;
                int r = e >> 6, c = e & 63;
                ST(r, c) = Arow[(long long)r * Sc + t * TILE + c];
            }
        }
        __syncthreads();
        // normalize own (2 rows x 8 keys) in St
        #pragma unroll
        for (int kk = 0; kk < KPW; kk++) {
            int j = w * KPW + kk;
            ST(r0, j) = ex2((ST(r0, j) - ml0) * LOG2E) * il0;
            ST(r1, j) = ex2((ST(r1, j) - ml1) * LOG2E) * il1;
        }
        __syncthreads();

        // PV: 64 keys, 8 d-cols, 2 rows
        #pragma unroll
        for (int jb = 0; jb < 16; jb++) {
            float4 pa = *reinterpret_cast<const float4*>(&ST(r0, 4 * jb));
            float4 pb = *reinterpret_cast<const float4*>(&ST(r1, 4 * jb));
            float paa[4] = {pa.x, pa.y, pa.z, pa.w};
            float pbb[4] = {pb.x, pb.y, pb.z, pb.w};
            #pragma unroll
            for (int u = 0; u < 4; u++) {
                int j = 4 * jb + u;
                ulonglong2 v0 = *reinterpret_cast<const ulonglong2*>(&KT(j, w * 8));
                ulonglong2 v1 = *reinterpret_cast<const ulonglong2*>(&KT(j, w * 8 + 4));
                uint64_t ppa = pack2(paa[u], paa[u]);
                uint64_t ppb = pack2(pbb[u], pbb[u]);
                fma2(cA[0], ppa, v0.x); fma2(cA[1], ppa, v0.y);
                fma2(cA[2], ppa, v1.x); fma2(cA[3], ppa, v1.y);
                fma2(cB[0], ppb, v0.x); fma2(cB[1], ppb, v0.y);
                fma2(cB[2], ppb, v1.x); fma2(cB[3], ppb, v1.y);
            }
        }
        // final attention tile -> gmem (coalesced)
        #pragma unroll
        for (int i = 0; i < 16; i++) {
            int e = tid + i * 256;
            int r = e >> 6, c = e & 63;
            Arow[(long long)r * Sc + t * TILE + c] = ST(r, c);
        }
    }

    // context write: lane's 2 rows x 8 cols
    {
        float o[8];
        unpack2(cA[0], o[0], o[1]); unpack2(cA[1], o[2], o[3]);
        unpack2(cA[2], o[4], o[5]); unpack2(cA[3], o[6], o[7]);
        float* cp = Crow + (long long)r0 * Dc + w * 8;
        *reinterpret_cast<float4*>(cp)     = make_float4(o[0], o[1], o[2], o[3]);
        *reinterpret_cast<float4*>(cp + 4) = make_float4(o[4], o[5], o[6], o[7]);
        unpack2(cB[0], o[0], o[1]); unpack2(cB[1], o[2], o[3]);
        unpack2(cB[2], o[4], o[5]); unpack2(cB[3], o[6], o[7]);
        cp = Crow + (long long)r1 * Dc + w * 8;
        *reinterpret_cast<float4*>(cp)     = make_float4(o[0], o[1], o[2], o[3]);
        *reinterpret_cast<float4*>(cp + 4) = make_float4(o[4], o[5], o[6], o[7]);
    }
}

extern "C" void kernel_launch(void* const* d_in, const int* in_sizes, int n_in,
                              void* d_out, int out_size)
{
    const float* Q = (const float*)d_in[0];
    const float* K = (const float*)d_in[1];
    const float* V = (const float*)d_in[2];
    const int*   M = (const int*)d_in[3];
    (void)in_sizes; (void)n_in; (void)out_size;

    float* ctx  = (float*)d_out;
    float* attn = (float*)d_out + (size_t)Bc * Hc * Sc * Dc;

    static bool attr_set = false;
    if (!attr_set) {
        cudaFuncSetAttribute(attn_fused_kernel,
                             cudaFuncAttributeMaxDynamicSharedMemorySize, SMEM_BYTES);
        attr_set = true;
    }

    dim3 grid(Sc / ROWS, Hc, Bc);   // (32, 16, 2)
    attn_fused_kernel<<<grid, 256, SMEM_BYTES>>>(Q, K, V, M, ctx, attn);
}